// round 7
// baseline (speedup 1.0000x reference)
#include <cuda_runtime.h>
#include <cstdint>

#define E_DIM 1024
#define T_DIM 8192

// Scratch: QKV for the 16384 dilated tokens, layout [row][384] = Q|K|V.
__device__ float g_qkv[16384 * 384];
// int8 limb planes (packed 4 per uint32)
__device__ uint32_t g_a8h[16384 * 256];
__device__ uint32_t g_a8l[16384 * 256];
__device__ uint32_t g_b8h[384 * 256];
__device__ uint32_t g_b8l[384 * 256];
// Gathered positional bias p_bias[k][o]
__device__ float g_pbias[64 * 64];

__device__ __forceinline__ uint32_t smem_u32(const void* p) {
    uint32_t a;
    asm("{ .reg .u64 t; cvta.to.shared.u64 t, %1; cvt.u32.u64 %0, t; }" : "=r"(a) : "l"(p));
    return a;
}

#define LDSM4(r, addr) \
    asm volatile("ldmatrix.sync.aligned.m8n8.x4.shared.b16 {%0,%1,%2,%3}, [%4];" \
        : "=r"((r)[0]), "=r"((r)[1]), "=r"((r)[2]), "=r"((r)[3]) : "r"(addr))

#define IMMA(c, a, b0, b1) \
    asm volatile("mma.sync.aligned.m16n8k32.row.col.s32.s8.s8.s32 " \
        "{%0,%1,%2,%3}, {%4,%5,%6,%7}, {%8,%9}, {%0,%1,%2,%3};" \
        : "+r"((c)[0]), "+r"((c)[1]), "+r"((c)[2]), "+r"((c)[3]) \
        : "r"((a)[0]), "r"((a)[1]), "r"((a)[2]), "r"((a)[3]), "r"(b0), "r"(b1))

__device__ __forceinline__ void cp16(uint32_t dst, const void* src) {
    asm volatile("cp.async.cg.shared.global [%0], [%1], 16;" :: "r"(dst), "l"(src));
}
#define CP_COMMIT() asm volatile("cp.async.commit_group;" ::: "memory")

// quantize 4 floats: v = clamp(rn(x*s), +-32639/32640), split v = 256*h + l
__device__ __forceinline__ void quant4(float4 v, float s, uint32_t& hw, uint32_t& lw) {
    int a[4] = {__float2int_rn(v.x * s), __float2int_rn(v.y * s),
                __float2int_rn(v.z * s), __float2int_rn(v.w * s)};
    hw = 0; lw = 0;
    #pragma unroll
    for (int i = 0; i < 4; i++) {
        int t = min(max(a[i], -32640), 32639);
        int h = (t + 128) >> 8;
        int l = t - (h << 8);
        hw |= (uint32_t)(h & 255) << (i * 8);
        lw |= (uint32_t)(l & 255) << (i * 8);
    }
}

// prep: quantize gathered X and W to int8 limbs; gather p_bias.
// blocks 0..16383: X row; 16384..16767: W row; 16768: p_bias.
__global__ __launch_bounds__(256) void prep_kernel(
    const float* __restrict__ x,
    const float* __restrict__ Wq, const float* __restrict__ Wk,
    const float* __restrict__ Wv, const float* __restrict__ P)
{
    const int blk = blockIdx.x;
    const int t = threadIdx.x;
    if (blk < 16384) {
        int b = blk >> 12, j = (blk >> 6) & 63, l = blk & 63;
        const float4* src = reinterpret_cast<const float4*>(
            x + ((size_t)b * T_DIM + (size_t)l * 128 + j) * E_DIM);
        uint32_t h, lo;
        quant4(src[t], 4096.0f, h, lo);
        g_a8h[(size_t)blk * 256 + t] = h;
        g_a8l[(size_t)blk * 256 + t] = lo;
    } else if (blk < 16768) {
        int r = blk - 16384;
        const float* W = (r < 128) ? Wq : (r < 256) ? Wk : Wv;
        const float4* src = reinterpret_cast<const float4*>(W + (size_t)(r & 127) * 1024);
        uint32_t h, lo;
        quant4(src[t], 32768.0f, h, lo);
        g_b8h[(size_t)r * 256 + t] = h;
        g_b8l[(size_t)r * 256 + t] = lo;
    } else {
        #pragma unroll
        for (int it = 0; it < 16; it++) {
            int i = t + it * 256;
            g_pbias[i] = P[(size_t)(i >> 6) * 128 * T_DIM + (size_t)(i & 63) * 128];
        }
    }
}

// ---- GEMM: C[16384,384] = Xdil * W^T via IMMA s8 2-limb, all 4 products
//      (hh w=65536, hl+lh w=256, ll w=1) -> exact 15x15-bit product.
// CTA 64x64, 128 threads, 4 warps (2M x 2N, warp tile 32x32), BK=32, 4 stages.
// Stage (10240B): A rows [hi 32B][lo 32B][pad 16] x64 @0; B same @5120.
__global__ __launch_bounds__(128, 3) void qkv_gemm_imma()
{
    __shared__ __align__(16) char dsm[4 * 10240];
    const uint32_t smem_base = smem_u32(dsm);
    const int tid = threadIdx.x;
    const int warp = tid >> 5, lane = tid & 31;
    const int nbase = blockIdx.x * 64;       // fast dim: column slab of 384
    const int m0 = blockIdx.y * 64;

    // loader: thread -> (row, 16B half); 4 cp16 per chunk
    const int lrow = tid >> 1;
    const int lh = (tid & 1) * 16;
    const char* sa_h = (const char*)g_a8h + (size_t)(m0 + lrow) * 1024 + lh;
    const char* sa_l = (const char*)g_a8l + (size_t)(m0 + lrow) * 1024 + lh;
    const char* sb_h = (const char*)g_b8h + (size_t)(nbase + lrow) * 1024 + lh;
    const char* sb_l = (const char*)g_b8l + (size_t)(nbase + lrow) * 1024 + lh;
    const uint32_t da = lrow * 80 + lh;
    const uint32_t db = 5120 + lrow * 80 + lh;

    auto issue_stage = [&](int slot, int k0) {
        uint32_t st = smem_base + slot * 10240;
        cp16(st + da, sa_h + k0);
        cp16(st + da + 32, sa_l + k0);
        cp16(st + db, sb_h + k0);
        cp16(st + db + 32, sb_l + k0);
    };

    // compute mapping: warp grid 2M x 2N, warp tile 32x32
    const int m_w = (warp >> 1) * 32;
    const int n_w = (warp & 1) * 32;

    int accH[2][4][4], accM[2][4][4], accL[2][4][4];
    #pragma unroll
    for (int i = 0; i < 2; i++)
        #pragma unroll
        for (int j = 0; j < 4; j++)
            #pragma unroll
            for (int k = 0; k < 4; k++) { accH[i][j][k] = 0; accM[i][j][k] = 0; accL[i][j][k] = 0; }

    issue_stage(0, 0);  CP_COMMIT();
    issue_stage(1, 32); CP_COMMIT();
    issue_stage(2, 64); CP_COMMIT();

    for (int c = 0; c < 32; c++) {
        asm volatile("cp.async.wait_group 2;" ::: "memory");
        __syncthreads();

        const uint32_t st = smem_base + (c & 3) * 10240;
        uint32_t ah[2][4], al[2][4], bh[2][4], bl[2][4];
        #pragma unroll
        for (int mt = 0; mt < 2; mt++) {
            uint32_t ra = st + (m_w + mt * 16 + (lane & 15)) * 80 + (lane >> 4) * 16;
            LDSM4(ah[mt], ra);
            LDSM4(al[mt], ra + 32);
        }
        #pragma unroll
        for (int q = 0; q < 2; q++) {
            uint32_t rb = st + 5120 + (n_w + q * 16 + (lane & 15)) * 80 + (lane >> 4) * 16;
            LDSM4(bh[q], rb);
            LDSM4(bl[q], rb + 32);
        }
        // hh -> accH (8 independent)
        #pragma unroll
        for (int mt = 0; mt < 2; mt++)
            #pragma unroll
            for (int nt = 0; nt < 4; nt++)
                IMMA(accH[mt][nt], ah[mt], bh[nt >> 1][nt & 1], bh[nt >> 1][(nt & 1) + 2]);
        // hl -> accM (8 independent)
        #pragma unroll
        for (int mt = 0; mt < 2; mt++)
            #pragma unroll
            for (int nt = 0; nt < 4; nt++)
                IMMA(accM[mt][nt], ah[mt], bl[nt >> 1][nt & 1], bl[nt >> 1][(nt & 1) + 2]);
        // ll -> accL (8 independent)
        #pragma unroll
        for (int mt = 0; mt < 2; mt++)
            #pragma unroll
            for (int nt = 0; nt < 4; nt++)
                IMMA(accL[mt][nt], al[mt], bl[nt >> 1][nt & 1], bl[nt >> 1][(nt & 1) + 2]);
        // lh -> accM (reuse 16 apart)
        #pragma unroll
        for (int mt = 0; mt < 2; mt++)
            #pragma unroll
            for (int nt = 0; nt < 4; nt++)
                IMMA(accM[mt][nt], al[mt], bh[nt >> 1][nt & 1], bh[nt >> 1][(nt & 1) + 2]);

        __syncthreads();
        if (c < 29) issue_stage((c + 3) & 3, (c + 3) * 32);
        CP_COMMIT();
    }

    // epilogue: C = 2^-27 * (65536*accH + 256*accM + accL)
    const float c1 = 4.8828125e-4f;        // 65536 * 2^-27
    const float c2 = 1.9073486328125e-6f;  // 256   * 2^-27
    const float c3 = 7.450580596923828e-9f; // 2^-27
    #pragma unroll
    for (int mt = 0; mt < 2; mt++) {
        #pragma unroll
        for (int nt = 0; nt < 4; nt++) {
            int row0 = m0 + m_w + mt * 16 + (lane >> 2);
            int col = nbase + n_w + nt * 8 + (lane & 3) * 2;
            float e[4];
            #pragma unroll
            for (int k = 0; k < 4; k++)
                e[k] = fmaf((float)accH[mt][nt][k], c1,
                       fmaf((float)accM[mt][nt][k], c2, (float)accL[mt][nt][k] * c3));
            *reinterpret_cast<float2*>(&g_qkv[(size_t)row0 * 384 + col]) = make_float2(e[0], e[1]);
            *reinterpret_cast<float2*>(&g_qkv[(size_t)(row0 + 8) * 384 + col]) = make_float2(e[2], e[3]);
        }
    }
}

// ---- attention: one block per (b,j) group; fused odd-row zeroing ----
__global__ __launch_bounds__(256) void attn_kernel(float* __restrict__ out)
{
    extern __shared__ float sm[];
    float* Ks  = sm;                 // [64][128]
    float* Vs  = Ks + 64 * 128;      // [64][128]
    float* QtS = Vs + 64 * 128;      // [128][65] Qt, later overlaid by S[64][65]
    const int g = blockIdx.x;
    const int bbk = g >> 6, jseg = g & 63;
    const int tid = threadIdx.x;
    const float* base = g_qkv + (size_t)g * 64 * 384;

    for (int idx = tid; idx < 64 * 32; idx += 256) {
        int row = idx >> 5;
        int c4 = (idx & 31) * 4;
        const float* rp = base + (size_t)row * 384;
        float4 qv = *reinterpret_cast<const float4*>(rp + c4);
        float4 kv = *reinterpret_cast<const float4*>(rp + 128 + c4);
        float4 vv = *reinterpret_cast<const float4*>(rp + 256 + c4);
        *reinterpret_cast<float4*>(Ks + row * 128 + c4) = kv;
        *reinterpret_cast<float4*>(Vs + row * 128 + c4) = vv;
        QtS[(c4 + 0) * 65 + row] = qv.x;
        QtS[(c4 + 1) * 65 + row] = qv.y;
        QtS[(c4 + 2) * 65 + row] = qv.z;
        QtS[(c4 + 3) * 65 + row] = qv.w;
    }
    __syncthreads();

    // S[k][o] = dot(K[k], Q[o]) in regs; then mask + bias + scale
    const int tk = tid >> 4, to = tid & 15;
    float sval[4][4];
    {
        float sacc[4][4];
        #pragma unroll
        for (int i = 0; i < 4; i++)
            #pragma unroll
            for (int j = 0; j < 4; j++) sacc[i][j] = 0.f;
        for (int p = 0; p < 128; p++) {
            float rk[4], rq[4];
            #pragma unroll
            for (int i = 0; i < 4; i++) rk[i] = Ks[(tk * 4 + i) * 128 + p];
            #pragma unroll
            for (int j = 0; j < 4; j++) rq[j] = QtS[p * 65 + to * 4 + j];
            #pragma unroll
            for (int i = 0; i < 4; i++)
                #pragma unroll
                for (int j = 0; j < 4; j++)
                    sacc[i][j] = fmaf(rk[i], rq[j], sacc[i][j]);
        }
        const float nf = 0.08838834764831845f;  // 1/sqrt(128)
        #pragma unroll
        for (int i = 0; i < 4; i++) {
            int k = tk * 4 + i;
            #pragma unroll
            for (int j = 0; j < 4; j++) {
                int o = to * 4 + j;
                float v = (k >= o) ? sacc[i][j] : -10000.0f;
                v += g_pbias[k * 64 + o];
                sval[i][j] = v * nf;
            }
        }
    }
    __syncthreads();   // all threads done reading Qt
    #pragma unroll
    for (int i = 0; i < 4; i++)
        #pragma unroll
        for (int j = 0; j < 4; j++)
            QtS[(tk * 4 + i) * 65 + to * 4 + j] = sval[i][j];
    __syncthreads();

    // softmax over k: o = tid>>2, 4 lanes x 16 k each, shfl-bfly reduce
    {
        const int o = tid >> 2, seg = tid & 3;
        float e[16];
        float mx = -3.402823466e38f;
        #pragma unroll
        for (int i = 0; i < 16; i++) {
            e[i] = QtS[(seg * 16 + i) * 65 + o];
            mx = fmaxf(mx, e[i]);
        }
        mx = fmaxf(mx, __shfl_xor_sync(0xffffffffu, mx, 1));
        mx = fmaxf(mx, __shfl_xor_sync(0xffffffffu, mx, 2));
        float ssum = 0.f;
        #pragma unroll
        for (int i = 0; i < 16; i++) { e[i] = __expf(e[i] - mx); ssum += e[i]; }
        ssum += __shfl_xor_sync(0xffffffffu, ssum, 1);
        ssum += __shfl_xor_sync(0xffffffffu, ssum, 2);
        float inv = 1.0f / ssum;
        #pragma unroll
        for (int i = 0; i < 16; i++)
            QtS[(seg * 16 + i) * 65 + o] = e[i] * inv;
    }
    __syncthreads();

    // att[d][m] = sum_k S[k][d] * V[k][m]; write even row, zero odd row
    {
        const int td = tid >> 4, tmm = tid & 15;
        float acc[4][8];
        #pragma unroll
        for (int i = 0; i < 4; i++)
            #pragma unroll
            for (int j = 0; j < 8; j++) acc[i][j] = 0.f;
        for (int k = 0; k < 64; k++) {
            float rs[4];
            #pragma unroll
            for (int i = 0; i < 4; i++) rs[i] = QtS[k * 65 + td * 4 + i];
            float4 v0 = *reinterpret_cast<const float4*>(Vs + k * 128 + tmm * 8);
            float4 v1 = *reinterpret_cast<const float4*>(Vs + k * 128 + tmm * 8 + 4);
            float rv[8] = {v0.x, v0.y, v0.z, v0.w, v1.x, v1.y, v1.z, v1.w};
            #pragma unroll
            for (int i = 0; i < 4; i++)
                #pragma unroll
                for (int j = 0; j < 8; j++)
                    acc[i][j] = fmaf(rs[i], rv[j], acc[i][j]);
        }
        const float4 z = make_float4(0.f, 0.f, 0.f, 0.f);
        #pragma unroll
        for (int i = 0; i < 4; i++) {
            int d = td * 4 + i;
            size_t orow = (size_t)bbk * T_DIM + 2 * ((size_t)jseg * 64 + d);
            float* op = out + orow * 128 + tmm * 8;
            *reinterpret_cast<float4*>(op)     = make_float4(acc[i][0], acc[i][1], acc[i][2], acc[i][3]);
            *reinterpret_cast<float4*>(op + 4) = make_float4(acc[i][4], acc[i][5], acc[i][6], acc[i][7]);
            float* oz = op + 128;   // odd row (poisoned) -> zero
            *reinterpret_cast<float4*>(oz)     = z;
            *reinterpret_cast<float4*>(oz + 4) = z;
        }
    }
}

extern "C" void kernel_launch(void* const* d_in, const int* in_sizes, int n_in,
                              void* d_out, int out_size) {
    const float* x  = (const float*)d_in[0];   // x_in  [4, 8192, 1024]
    const float* P  = (const float*)d_in[1];   // P     [8192, 8192]
    const float* Wk = (const float*)d_in[2];   // Wk    [128, 1024]
    const float* Wq = (const float*)d_in[3];   // Wq    [128, 1024]
    const float* Wv = (const float*)d_in[4];   // Wv    [128, 1024]
    float* out = (float*)d_out;                // [4, 8192, 128] fp32

    prep_kernel<<<16769, 256>>>(x, Wq, Wk, Wv, P);

    qkv_gemm_imma<<<dim3(6, 256), 128>>>();

    int asm_sz = (64 * 128 * 2 + 128 * 65) * (int)sizeof(float);  // 98816
    cudaFuncSetAttribute(attn_kernel, cudaFuncAttributeMaxDynamicSharedMemorySize, asm_sz);
    attn_kernel<<<256, 256, asm_sz>>>(out);
}

// round 8
// speedup vs baseline: 2.3874x; 2.3874x over previous
#include <cuda_runtime.h>
#include <cuda_bf16.h>
#include <cstdint>

#define E_DIM 1024
#define T_DIM 8192

// Scratch: QKV for the 16384 dilated tokens, layout [row][384] = Q|K|V.
__device__ float g_qkv[16384 * 384];
// Pre-split weights, rows 0-127=Wq, 128-255=Wk, 256-383=Wv
__device__ __nv_bfloat16 g_whi[384 * 1024];
__device__ __nv_bfloat16 g_wlo[384 * 1024];
// Gathered positional bias p_bias[k][o]
__device__ float g_pbias[64 * 64];
// Per-m-block completion counters (3 slabs each)
__device__ int g_ready[128];

__device__ __forceinline__ uint32_t smem_u32(const void* p) {
    uint32_t a;
    asm("{ .reg .u64 t; cvta.to.shared.u64 t, %1; cvt.u32.u64 %0, t; }" : "=r"(a) : "l"(p));
    return a;
}

#define LDSM4(r, addr) \
    asm volatile("ldmatrix.sync.aligned.m8n8.x4.shared.b16 {%0,%1,%2,%3}, [%4];" \
        : "=r"((r)[0]), "=r"((r)[1]), "=r"((r)[2]), "=r"((r)[3]) : "r"(addr))

#define MMA16816(c, a, b0, b1) \
    asm volatile("mma.sync.aligned.m16n8k16.row.col.f32.bf16.bf16.f32 " \
        "{%0,%1,%2,%3}, {%4,%5,%6,%7}, {%8,%9}, {%0,%1,%2,%3};" \
        : "+f"((c)[0]), "+f"((c)[1]), "+f"((c)[2]), "+f"((c)[3]) \
        : "r"((a)[0]), "r"((a)[1]), "r"((a)[2]), "r"((a)[3]), "r"(b0), "r"(b1))

__device__ __forceinline__ void cp16(uint32_t dst, const void* src) {
    asm volatile("cp.async.cg.shared.global [%0], [%1], 16;" :: "r"(dst), "l"(src));
}
#define CP_COMMIT() asm volatile("cp.async.commit_group;" ::: "memory")

__device__ __forceinline__ void split2(float a, float b, uint32_t& hi, uint32_t& lo) {
    __nv_bfloat162 h = __floats2bfloat162_rn(a, b);
    __nv_bfloat162 l = __floats2bfloat162_rn(a - __bfloat162float(h.x),
                                             b - __bfloat162float(h.y));
    hi = *reinterpret_cast<uint32_t*>(&h);
    lo = *reinterpret_cast<uint32_t*>(&l);
}

// prep: split weights to bf16 hi/lo; gather p_bias; reset ready counters.
__global__ __launch_bounds__(256) void prep_kernel(
    const float* __restrict__ Wq, const float* __restrict__ Wk,
    const float* __restrict__ Wv, const float* __restrict__ P)
{
    int i = blockIdx.x * blockDim.x + threadIdx.x;
    if (i < 128) g_ready[i] = 0;
    if (i < 4096) {
        g_pbias[i] = P[(size_t)(i >> 6) * 128 * T_DIM + (size_t)(i & 63) * 128];
    }
    if (i >= 384 * 1024) return;
    int r = i >> 10;
    const float* W = (r < 128) ? Wq : (r < 256) ? Wk : Wv;
    float v = W[(size_t)(r & 127) * 1024 + (i & 1023)];
    __nv_bfloat16 h = __float2bfloat16(v);
    g_whi[i] = h;
    g_wlo[i] = __float2bfloat16(v - __bfloat162float(h));
}

// ---- fused GEMM+attention kernel ----
// bids 0..383:  GEMM slab = bid%3, m-block = bid/3 (adjacent bids finish one m-block)
// bids 384..639: attention group g = bid-384, waits on g_ready[g>>1] == 3
#define STG   38912
#define BH_OFF 18432

__global__ __launch_bounds__(256, 2) void fused_kernel(
    const float* __restrict__ x, float* __restrict__ out)
{
    extern __shared__ char dsm[];
    const int bid = blockIdx.x;
    const int tid = threadIdx.x;

    if (bid < 384) {
        // ================= GEMM part (R5-proven) =================
        const uint32_t smem_base = smem_u32(dsm);
        const int warp = tid >> 5, lane = tid & 31;
        const int nbase = (bid % 3) * 128;
        const int m0 = (bid / 3) * 128;

        const float* axp[4];
        const int arow_sub = tid >> 3;
        #pragma unroll
        for (int q = 0; q < 4; q++) {
            int r = m0 + arow_sub + q * 32;
            int b = r >> 12, j = (r >> 6) & 63, l = r & 63;
            axp[q] = x + ((size_t)b * T_DIM + (size_t)l * 128 + j) * E_DIM + (tid & 7) * 4;
        }
        const int brow_sub = tid >> 2;
        const __nv_bfloat16 *bhp[2], *blp[2];
        #pragma unroll
        for (int q = 0; q < 2; q++) {
            size_t off = (size_t)(nbase + brow_sub + q * 64) * 1024 + (tid & 3) * 8;
            bhp[q] = g_whi + off;
            blp[q] = g_wlo + off;
        }
        const uint32_t a_dst0 = arow_sub * 144 + (tid & 7) * 16;
        const uint32_t b_dst0 = brow_sub * 80 + (tid & 3) * 16;

        auto issue_stage = [&](int slot, int k0) {
            uint32_t sb = smem_base + slot * STG;
            #pragma unroll
            for (int q = 0; q < 4; q++)
                cp16(sb + a_dst0 + q * 4608, axp[q] + k0);
            #pragma unroll
            for (int q = 0; q < 2; q++) {
                cp16(sb + BH_OFF + b_dst0 + q * 5120, bhp[q] + k0);
                cp16(sb + BH_OFF + 10240 + b_dst0 + q * 5120, blp[q] + k0);
            }
        };

        const int m_w = (warp >> 1) * 32;
        const int n_w = (warp & 1) * 64;

        float acc[2][8][4];
        #pragma unroll
        for (int i = 0; i < 2; i++)
            #pragma unroll
            for (int j = 0; j < 8; j++)
                #pragma unroll
                for (int k = 0; k < 4; k++) acc[i][j][k] = 0.f;

        issue_stage(0, 0);  CP_COMMIT();
        issue_stage(1, 32); CP_COMMIT();

        for (int c = 0; c < 32; c++) {
            asm volatile("cp.async.wait_group 1;" ::: "memory");
            __syncthreads();

            const int slot = c & 1;
            const float* Asm = reinterpret_cast<const float*>(dsm + slot * STG);
            const uint32_t bb = smem_base + slot * STG + BH_OFF;

            #pragma unroll
            for (int kst = 0; kst < 2; kst++) {
                uint32_t ah[2][4], al[2][4];
                #pragma unroll
                for (int mt = 0; mt < 2; mt++) {
                    const float* ap = Asm + (m_w + mt * 16 + (lane >> 2)) * 36
                                    + kst * 16 + (lane & 3) * 2;
                    float2 v00 = *reinterpret_cast<const float2*>(ap);
                    float2 v10 = *reinterpret_cast<const float2*>(ap + 8 * 36);
                    float2 v01 = *reinterpret_cast<const float2*>(ap + 8);
                    float2 v11 = *reinterpret_cast<const float2*>(ap + 8 * 36 + 8);
                    split2(v00.x, v00.y, ah[mt][0], al[mt][0]);
                    split2(v10.x, v10.y, ah[mt][1], al[mt][1]);
                    split2(v01.x, v01.y, ah[mt][2], al[mt][2]);
                    split2(v11.x, v11.y, ah[mt][3], al[mt][3]);
                }
                #pragma unroll
                for (int nh = 0; nh < 2; nh++) {
                    uint32_t bh[2][4], bl[2][4];
                    #pragma unroll
                    for (int q = 0; q < 2; q++) {
                        uint32_t rb = bb + (n_w + nh * 32 + q * 16 + (lane & 15)) * 80
                                    + kst * 32 + (lane >> 4) * 16;
                        LDSM4(bh[q], rb);
                        LDSM4(bl[q], rb + 10240);
                    }
                    #pragma unroll
                    for (int mt = 0; mt < 2; mt++)
                        #pragma unroll
                        for (int t = 0; t < 4; t++) {
                            const int q = t >> 1, s = t & 1;
                            MMA16816(acc[mt][nh * 4 + q * 2 + s], ah[mt], bh[q][s], bh[q][s + 2]);
                        }
                    #pragma unroll
                    for (int mt = 0; mt < 2; mt++)
                        #pragma unroll
                        for (int t = 0; t < 4; t++) {
                            const int q = t >> 1, s = t & 1;
                            MMA16816(acc[mt][nh * 4 + q * 2 + s], ah[mt], bl[q][s], bl[q][s + 2]);
                        }
                    #pragma unroll
                    for (int mt = 0; mt < 2; mt++)
                        #pragma unroll
                        for (int t = 0; t < 4; t++) {
                            const int q = t >> 1, s = t & 1;
                            MMA16816(acc[mt][nh * 4 + q * 2 + s], al[mt], bh[q][s], bh[q][s + 2]);
                        }
                }
            }

            __syncthreads();
            if (c < 30) issue_stage(slot, (c + 2) * 32);
            CP_COMMIT();
        }

        #pragma unroll
        for (int mt = 0; mt < 2; mt++) {
            #pragma unroll
            for (int nt = 0; nt < 8; nt++) {
                int row0 = m0 + m_w + mt * 16 + (lane >> 2);
                int col = nbase + n_w + nt * 8 + (lane & 3) * 2;
                float* p0 = &g_qkv[(size_t)row0 * 384 + col];
                float* p1 = &g_qkv[(size_t)(row0 + 8) * 384 + col];
                *reinterpret_cast<float2*>(p0) = make_float2(acc[mt][nt][0], acc[mt][nt][1]);
                *reinterpret_cast<float2*>(p1) = make_float2(acc[mt][nt][2], acc[mt][nt][3]);
            }
        }
        __threadfence();
        __syncthreads();
        if (tid == 0) atomicAdd(&g_ready[bid / 3], 1);

    } else {
        // ================= attention part =================
        float* sm = reinterpret_cast<float*>(dsm);
        float* Kt  = sm;                  // [128][68] transposed: Kt[p][k]
        float* Vs  = Kt + 128 * 68;       // [64][128]
        float* QtS = Vs + 64 * 128;       // [128][68] Qt[p][o], overlaid by S[64][68]
        const int g = bid - 384;
        const int mb = g >> 1;
        const int bbk = g >> 6, jseg = g & 63;
        const float* base = g_qkv + (size_t)g * 64 * 384;

        // wait for all 3 slabs of this m-block
        if (tid == 0) {
            int v;
            do {
                asm volatile("ld.acquire.gpu.s32 %0, [%1];" : "=r"(v) : "l"(g_ready + mb));
                if (v < 3) __nanosleep(128);
            } while (v < 3);
        }
        __syncthreads();

        for (int idx = tid; idx < 64 * 32; idx += 256) {
            int row = idx >> 5;
            int c4 = (idx & 31) * 4;
            const float* rp = base + (size_t)row * 384;
            float4 qv = *reinterpret_cast<const float4*>(rp + c4);
            float4 kv = *reinterpret_cast<const float4*>(rp + 128 + c4);
            float4 vv = *reinterpret_cast<const float4*>(rp + 256 + c4);
            *reinterpret_cast<float4*>(Vs + row * 128 + c4) = vv;
            Kt[(c4 + 0) * 68 + row] = kv.x;
            Kt[(c4 + 1) * 68 + row] = kv.y;
            Kt[(c4 + 2) * 68 + row] = kv.z;
            Kt[(c4 + 3) * 68 + row] = kv.w;
            QtS[(c4 + 0) * 68 + row] = qv.x;
            QtS[(c4 + 1) * 68 + row] = qv.y;
            QtS[(c4 + 2) * 68 + row] = qv.z;
            QtS[(c4 + 3) * 68 + row] = qv.w;
        }
        __syncthreads();

        // S[k][o] = dot(K[k], Q[o]); float4 LDS from transposed tiles
        const int tk = tid >> 4, to = tid & 15;
        float4 sval[4];
        {
            float sacc[4][4];
            #pragma unroll
            for (int i = 0; i < 4; i++)
                #pragma unroll
                for (int j = 0; j < 4; j++) sacc[i][j] = 0.f;
            for (int p = 0; p < 128; p++) {
                float4 rk = *reinterpret_cast<const float4*>(Kt + p * 68 + tk * 4);
                float4 rq = *reinterpret_cast<const float4*>(QtS + p * 68 + to * 4);
                float ka[4] = {rk.x, rk.y, rk.z, rk.w};
                float qa[4] = {rq.x, rq.y, rq.z, rq.w};
                #pragma unroll
                for (int i = 0; i < 4; i++)
                    #pragma unroll
                    for (int j = 0; j < 4; j++)
                        sacc[i][j] = fmaf(ka[i], qa[j], sacc[i][j]);
            }
            const float nf = 0.08838834764831845f;  // 1/sqrt(128)
            #pragma unroll
            for (int i = 0; i < 4; i++) {
                int k = tk * 4 + i;
                float e[4];
                #pragma unroll
                for (int j = 0; j < 4; j++) {
                    int o = to * 4 + j;
                    float v = (k >= o) ? sacc[i][j] : -10000.0f;
                    v += g_pbias[k * 64 + o];
                    e[j] = v * nf;
                }
                sval[i] = make_float4(e[0], e[1], e[2], e[3]);
            }
        }
        __syncthreads();   // done reading Qt
        #pragma unroll
        for (int i = 0; i < 4; i++)
            *reinterpret_cast<float4*>(QtS + (tk * 4 + i) * 68 + to * 4) = sval[i];
        __syncthreads();

        // softmax over k: o = tid>>2, 4 lanes x 16 k each
        {
            const int o = tid >> 2, seg = tid & 3;
            float e[16];
            float mx = -3.402823466e38f;
            #pragma unroll
            for (int i = 0; i < 16; i++) {
                e[i] = QtS[(seg * 16 + i) * 68 + o];
                mx = fmaxf(mx, e[i]);
            }
            mx = fmaxf(mx, __shfl_xor_sync(0xffffffffu, mx, 1));
            mx = fmaxf(mx, __shfl_xor_sync(0xffffffffu, mx, 2));
            float ssum = 0.f;
            #pragma unroll
            for (int i = 0; i < 16; i++) { e[i] = __expf(e[i] - mx); ssum += e[i]; }
            ssum += __shfl_xor_sync(0xffffffffu, ssum, 1);
            ssum += __shfl_xor_sync(0xffffffffu, ssum, 2);
            float inv = 1.0f / ssum;
            #pragma unroll
            for (int i = 0; i < 16; i++)
                QtS[(seg * 16 + i) * 68 + o] = e[i] * inv;
        }
        __syncthreads();

        // att[d][m] = sum_k S[k][d] * V[k][m]; write even row, zero odd row
        {
            const int td = tid >> 4, tmm = tid & 15;
            float acc[4][8];
            #pragma unroll
            for (int i = 0; i < 4; i++)
                #pragma unroll
                for (int j = 0; j < 8; j++) acc[i][j] = 0.f;
            for (int k = 0; k < 64; k++) {
                float4 rs4 = *reinterpret_cast<const float4*>(QtS + k * 68 + td * 4);
                float rs[4] = {rs4.x, rs4.y, rs4.z, rs4.w};
                float4 v0 = *reinterpret_cast<const float4*>(Vs + k * 128 + tmm * 8);
                float4 v1 = *reinterpret_cast<const float4*>(Vs + k * 128 + tmm * 8 + 4);
                float rv[8] = {v0.x, v0.y, v0.z, v0.w, v1.x, v1.y, v1.z, v1.w};
                #pragma unroll
                for (int i = 0; i < 4; i++)
                    #pragma unroll
                    for (int j = 0; j < 8; j++)
                        acc[i][j] = fmaf(rs[i], rv[j], acc[i][j]);
            }
            const float4 z = make_float4(0.f, 0.f, 0.f, 0.f);
            #pragma unroll
            for (int i = 0; i < 4; i++) {
                int d = td * 4 + i;
                size_t orow = (size_t)bbk * T_DIM + 2 * ((size_t)jseg * 64 + d);
                float* op = out + orow * 128 + tmm * 8;
                *reinterpret_cast<float4*>(op)     = make_float4(acc[i][0], acc[i][1], acc[i][2], acc[i][3]);
                *reinterpret_cast<float4*>(op + 4) = make_float4(acc[i][4], acc[i][5], acc[i][6], acc[i][7]);
                float* oz = op + 128;   // odd row (poisoned) -> zero
                *reinterpret_cast<float4*>(oz)     = z;
                *reinterpret_cast<float4*>(oz + 4) = z;
            }
        }
    }
}

extern "C" void kernel_launch(void* const* d_in, const int* in_sizes, int n_in,
                              void* d_out, int out_size) {
    const float* x  = (const float*)d_in[0];   // x_in  [4, 8192, 1024]
    const float* P  = (const float*)d_in[1];   // P     [8192, 8192]
    const float* Wk = (const float*)d_in[2];   // Wk    [128, 1024]
    const float* Wq = (const float*)d_in[3];   // Wq    [128, 1024]
    const float* Wv = (const float*)d_in[4];   // Wv    [128, 1024]
    float* out = (float*)d_out;                // [4, 8192, 128] fp32

    prep_kernel<<<1536, 256>>>(Wq, Wk, Wv, P);

    // attn smem need: (128*68 + 64*128 + 128*68)*4 = 102400 B  (> GEMM's 77824)
    int fsm = 102400;
    cudaFuncSetAttribute(fused_kernel, cudaFuncAttributeMaxDynamicSharedMemorySize, fsm);
    fused_kernel<<<640, 256, fsm>>>(x, out);
}